// round 16
// baseline (speedup 1.0000x reference)
#include <cuda_runtime.h>
#include <cuda_bf16.h>
#include <cuda_fp16.h>
#include <cstdint>
#include <math.h>

// ---------------- problem constants ----------------
#define T_STEPS 512
#define B_SZ    64
#define D_SZ    512
#define H_SZ    1024
#define G4      4096          // 4*H
#define BH      (B_SZ*H_SZ)   // 65536
#define NCTA    128

// ---------------- global scratch / sync state ----------------
__device__ float g_xg[(size_t)T_STEPS * B_SZ * G4];   // 512 MB, Xg = X@Wx + b
__device__ __half g_Hf[2][BH];                        // H fp16, ping-pong
__device__ __half g_Xf[(size_t)T_STEPS * B_SZ * D_SZ];   // X fp16
__device__ __half g_Wxf[(size_t)D_SZ * G4];           // Wx concat fp16
__device__ float g_bcat[G4];                          // bias concat
__device__ int      g_ready[NCTA];                    // per-CTA step counter
__device__ unsigned g_arrive = 0;
__device__ unsigned g_gen    = 0;

// ---------------- helpers ----------------
__device__ __forceinline__ uint32_t smem_u32(const void* p) {
    uint32_t a;
    asm("{ .reg .u64 t; cvta.to.shared.u64 t, %1; cvt.u32.u64 %0, t; }" : "=r"(a) : "l"(p));
    return a;
}
__device__ __forceinline__ void ldsm_x4(uint32_t* r, uint32_t addr) {
    asm volatile("ldmatrix.sync.aligned.m8n8.x4.shared.b16 {%0,%1,%2,%3}, [%4];"
                 : "=r"(r[0]), "=r"(r[1]), "=r"(r[2]), "=r"(r[3]) : "r"(addr));
}
__device__ __forceinline__ void ldsm_x4t(uint32_t* r, uint32_t addr) {
    asm volatile("ldmatrix.sync.aligned.m8n8.x4.trans.shared.b16 {%0,%1,%2,%3}, [%4];"
                 : "=r"(r[0]), "=r"(r[1]), "=r"(r[2]), "=r"(r[3]) : "r"(addr));
}
// fp16 mma
__device__ __forceinline__ void mma16816h(float* c, const unsigned* a, uint32_t b0, uint32_t b1) {
    asm volatile(
        "mma.sync.aligned.m16n8k16.row.col.f32.f16.f16.f32 "
        "{%0,%1,%2,%3}, {%4,%5,%6,%7}, {%8,%9}, {%0,%1,%2,%3};"
        : "+f"(c[0]), "+f"(c[1]), "+f"(c[2]), "+f"(c[3])
        : "r"(a[0]), "r"(a[1]), "r"(a[2]), "r"(a[3]), "r"(b0), "r"(b1));
}
__device__ __forceinline__ void cp16(uint32_t saddr, const void* g) {
    asm volatile("cp.async.cg.shared.global [%0], [%1], 16;" :: "r"(saddr), "l"(g));
}
#define CP_COMMIT() asm volatile("cp.async.commit_group;" ::: "memory")
#define CP_WAIT(N)  asm volatile("cp.async.wait_group %0;" :: "n"(N) : "memory")

__device__ __forceinline__ int flag_acq(const int* addr) {
    int v;
    asm volatile("ld.acquire.gpu.s32 %0, [%1];" : "=r"(v) : "l"(addr) : "memory");
    return v;
}
__device__ __forceinline__ void wait_ready_hot(int idx, int target) {
    const int* a = g_ready + idx;
    int spins = 0;
    while (flag_acq(a) < target) {
        if (++spins > 64) __nanosleep(32);
    }
}
// release-increment of this CTA's flag (pairs with consumers' ld.acquire)
__device__ __forceinline__ void flag_release_add(int* addr) {
    asm volatile("red.release.gpu.global.add.s32 [%0], 1;" :: "l"(addr) : "memory");
}

// self-resetting generation barrier (replay-safe)
__device__ __forceinline__ void init_barrier() {
    __syncthreads();
    if (threadIdx.x == 0) {
        __threadfence();
        unsigned gen;
        asm volatile("ld.acquire.gpu.u32 %0, [%1];" : "=r"(gen) : "l"(&g_gen) : "memory");
        unsigned old = atomicAdd(&g_arrive, 1u);
        if (old == NCTA - 1) {
            atomicExch(&g_arrive, 0u);
            __threadfence();
            atomicAdd(&g_gen, 1u);
        } else {
            unsigned cur;
            do {
                __nanosleep(64);
                asm volatile("ld.acquire.gpu.u32 %0, [%1];" : "=r"(cur) : "l"(&g_gen) : "memory");
            } while (cur == gen);
        }
        __threadfence();
    }
    __syncthreads();
}

// ====================================================================
// Kernel 0: convert X and Wx (concat) to fp16; build bias concat.
// (unchanged from passing R13)
// ====================================================================
#define NX4 ((size_t)T_STEPS * B_SZ * D_SZ / 4)      // 4,194,304
#define NW4 ((size_t)D_SZ * G4 / 4)                  // 524,288

__global__ void __launch_bounds__(256) conv_prep(
    const float* __restrict__ X,
    const float* __restrict__ Wx0, const float* __restrict__ Wx1,
    const float* __restrict__ Wx2, const float* __restrict__ Wx3,
    const float* __restrict__ b0p, const float* __restrict__ b1p,
    const float* __restrict__ b2p, const float* __restrict__ b3p)
{
    size_t i = (size_t)blockIdx.x * 256 + threadIdx.x;
    if (i < NX4) {
        float4 v = ((const float4*)X)[i];
        __half h0 = __float2half_rn(v.x), h1 = __float2half_rn(v.y);
        __half h2 = __float2half_rn(v.z), h3 = __float2half_rn(v.w);
        unsigned a = (unsigned)*(unsigned short*)&h0 | ((unsigned)*(unsigned short*)&h1 << 16);
        unsigned b = (unsigned)*(unsigned short*)&h2 | ((unsigned)*(unsigned short*)&h3 << 16);
        *(uint2*)&g_Xf[i * 4] = make_uint2(a, b);
    } else if (i < NX4 + NW4) {
        size_t d = i - NX4;
        int k  = (int)(d >> 10);
        int c4 = (int)(d & 1023);
        int col  = c4 * 4;
        int gate = col >> 10;
        int n    = col & 1023;
        const float* W = (gate == 0) ? Wx0 : (gate == 1) ? Wx1 : (gate == 2) ? Wx2 : Wx3;
        float4 v = *(const float4*)&W[(size_t)k * 1024 + n];
        __half h0 = __float2half_rn(v.x), h1 = __float2half_rn(v.y);
        __half h2 = __float2half_rn(v.z), h3 = __float2half_rn(v.w);
        unsigned a = (unsigned)*(unsigned short*)&h0 | ((unsigned)*(unsigned short*)&h1 << 16);
        unsigned b = (unsigned)*(unsigned short*)&h2 | ((unsigned)*(unsigned short*)&h3 << 16);
        *(uint2*)&g_Wxf[d * 4] = make_uint2(a, b);
    }
    if (i < G4 / 4) {
        int col = (int)i * 4;
        int gate = col >> 10, n = col & 1023;
        const float* bg = (gate == 0) ? b0p : (gate == 1) ? b1p : (gate == 2) ? b2p : b3p;
        ((float4*)g_bcat)[i] = *(const float4*)&bg[n];
    }
}

// ====================================================================
// Kernel 1: Xg = X @ Wxcat + bcat, single-pass fp16 mma.sync.
// (unchanged from passing R13)
// ====================================================================
#define XA(buf) ((buf)*18432)                      // [128][72] fp16
#define XB(buf) (36864 + (buf)*17408)              // [64][136] fp16
#define XG_SMEM 71680

__global__ void __launch_bounds__(256, 2) xg_mma()
{
    extern __shared__ char smc[];
    const uint32_t smem_base = smem_u32(smc);
    const int tid  = threadIdx.x;
    const int wid  = tid >> 5;
    const int lane = tid & 31;
    const int m0   = blockIdx.y * 128;
    const int nb   = blockIdx.x * 128;
    const int mw   = (wid & 3) * 32;
    const int nw   = (wid >> 2) * 64;

    const int arow = ((lane >> 3) & 1) * 8 + (lane & 7);
    const int acol = (lane >> 4) * 8;
    const int brow = ((lane >> 3) & 1) * 8 + (lane & 7);
    const int bcol = (lane >> 4) * 8;

    float acc[2][8][4];
    #pragma unroll
    for (int m = 0; m < 2; ++m)
        #pragma unroll
        for (int n = 0; n < 8; ++n)
            #pragma unroll
            for (int q = 0; q < 4; ++q) acc[m][n][q] = 0.f;

    auto issue_chunk = [&](int s, int buf) {
        #pragma unroll
        for (int i = 0; i < 4; ++i) {
            int idx = tid + i * 256;
            int row = idx >> 3, c8 = (idx & 7) * 8;
            uint32_t sa = smem_base + XA(buf) + (uint32_t)(row * 72 + c8) * 2u;
            cp16(sa, g_Xf + (size_t)(m0 + row) * D_SZ + s * 64 + c8);
        }
        #pragma unroll
        for (int i = 0; i < 4; ++i) {
            int idx = tid + i * 256;
            int r = idx >> 4, c8 = (idx & 15) * 8;
            uint32_t sb = smem_base + XB(buf) + (uint32_t)(r * 136 + c8) * 2u;
            cp16(sb, g_Wxf + (size_t)(s * 64 + r) * G4 + nb + c8);
        }
        CP_COMMIT();
    };

    issue_chunk(0, 0);
    #pragma unroll 1
    for (int s = 0; s < 8; ++s) {
        if (s < 7) { issue_chunk(s + 1, (s + 1) & 1); CP_WAIT(1); }
        else       { CP_WAIT(0); }
        __syncthreads();

        const int buf = s & 1;
        const uint32_t Ah = smem_base + XA(buf);
        const uint32_t Bh = smem_base + XB(buf);
        #pragma unroll
        for (int kt = 0; kt < 4; ++kt) {
            uint32_t ah[2][4];
            #pragma unroll
            for (int m = 0; m < 2; ++m)
                ldsm_x4(ah[m], Ah + (uint32_t)((mw + m * 16 + arow) * 72 + kt * 16 + acol) * 2u);
            uint32_t bh[4][4];
            #pragma unroll
            for (int np = 0; np < 4; ++np)
                ldsm_x4t(bh[np], Bh + (uint32_t)((kt * 16 + brow) * 136 + nw + np * 16 + bcol) * 2u);
            #pragma unroll
            for (int m = 0; m < 2; ++m)
                #pragma unroll
                for (int np = 0; np < 4; ++np) {
                    mma16816h(acc[m][2*np],   ah[m], bh[np][0], bh[np][1]);
                    mma16816h(acc[m][2*np+1], ah[m], bh[np][2], bh[np][3]);
                }
        }
        __syncthreads();
    }

    const int r0    = m0 + mw + (lane >> 2);
    const int cbase = nb + nw + (lane & 3) * 2;
    #pragma unroll
    for (int m = 0; m < 2; ++m) {
        #pragma unroll
        for (int nt = 0; nt < 8; ++nt) {
            int col = cbase + nt * 8;
            float b0 = g_bcat[col], b1 = g_bcat[col + 1];
            int rr = r0 + m * 16;
            float* p0 = g_xg + (size_t)rr * G4 + col;
            float* p1 = g_xg + (size_t)(rr + 8) * G4 + col;
            *(float2*)p0 = make_float2(acc[m][nt][0] + b0, acc[m][nt][1] + b1);
            *(float2*)p1 = make_float2(acc[m][nt][2] + b0, acc[m][nt][3] + b1);
        }
    }
}

// ====================================================================
// Kernel 2: persistent recurrence v9b — direct-LDG A operand.
// FIX vs R15: a1/a3 come from row r+8 => offset 8*(H_SZ/2) unsigneds
// (R15 had 4*(H_SZ/2) = +4 rows -> wrong rows -> rel_err 0.11).
// Fragment map (PTX m16n8k16 A, row-major): r=lane>>2, c=(lane&3)*2;
//   a0=H[r][c,c+1]  a1=H[r+8][c,c+1]  a2=H[r][c+8,c+9]  a3=H[r+8][c+8,c+9]
// 256 threads / 8 warps; warp w owns K-slice [w*128,+128), all 32 cols.
// B register-resident (64 regs); partials overlay init W staging.
// ====================================================================

#define RT9 81920                     // smem: max(W stage 81920, partials 69632)
#define ROWSTEP8 (8 * (H_SZ / 2))     // +8 H rows in unsigned units = 4096

__global__ void __launch_bounds__(256, 1) lstm_rec(
    const float* __restrict__ Wh0, const float* __restrict__ Wh1,
    const float* __restrict__ Wh2, const float* __restrict__ Wh3,
    float* __restrict__ out, int out_size)
{
    extern __shared__ char smc[];
    const uint32_t smem_base = smem_u32(smc);
    const int tid  = threadIdx.x;
    const int wid  = tid >> 5;
    const int lane = tid & 31;
    const int h0   = blockIdx.x * 8;

    if (tid == 0) g_ready[blockIdx.x] = 0;

    // ---- stage W slice fp16 (stride 40 halves, temp at offset 0) ----
    {
        __half* w = (__half*)smc;
        for (int i = tid; i < 32 * 1024; i += 256) {
            int k = i >> 5, n = i & 31;
            int gate = n >> 3;
            const float* W = (gate == 0) ? Wh0 : (gate == 1) ? Wh1
                             : (gate == 2) ? Wh2 : Wh3;
            w[k * 40 + n] = __float2half_rn(W[(size_t)k * H_SZ + h0 + (n & 7)]);
        }
    }
    __syncthreads();

    // ---- extract register-resident B fragments (once): 32 cols, K=128 ----
    const int brow  = ((lane >> 3) & 1) * 8 + (lane & 7);
    const int bcol0 = (lane >> 4) * 8;
    uint32_t bf[8][8];                 // [k-tile][half*4 + j]
    #pragma unroll
    for (int kt = 0; kt < 8; ++kt) {
        #pragma unroll
        for (int half = 0; half < 2; ++half) {
            uint32_t off = (uint32_t)((wid * 128 + kt * 16 + brow) * 40
                                      + half * 16 + bcol0) * 2u;
            ldsm_x4t(&bf[kt][half * 4], smem_base + off);
        }
    }
    init_barrier();   // flags reset visible; W area now reused for partials

    // ---- A direct-load geometry ----
    const int ar = lane >> 2;          // fragment row within 16
    const int ac = (lane & 3) * 2;     // fragment col (k) within 16, 4B-aligned
    // epilogue mapping
    const int b2 = tid >> 2;
    const int hq = (tid & 3) * 2;
    const size_t hidx = (size_t)b2 * H_SZ + h0 + hq;

    float* P  = (float*)smc;           // partials: 8 x [64][34] f32
    float* Pw = P + wid * 2176;

    float c0 = 0.f, c1 = 0.f;

    for (int t = 0; t < T_STEPS; ++t) {
        float acc[4][4][4];
        #pragma unroll
        for (int m = 0; m < 4; ++m)
            #pragma unroll
            for (int n = 0; n < 4; ++n)
                #pragma unroll
                for (int q = 0; q < 4; ++q) acc[m][n][q] = 0.f;

        // ---- Xg prefetch into registers ----
        const float* xb = g_xg + ((size_t)t * B_SZ + b2) * G4 + h0 + hq;
        float2 xv0 = __ldcg((const float2*)xb);
        float2 xv1 = __ldcg((const float2*)(xb + 1024));
        float2 xv2 = __ldcg((const float2*)(xb + 2048));
        float2 xv3 = __ldcg((const float2*)(xb + 3072));

        if (t > 0) {
            const __half* Hf = g_Hf[(t - 1) & 1];

            // wait the 16 producers of this K-slice (16 lanes in parallel)
            if (lane < 16) wait_ready_hot(wid * 16 + lane, t);
            __syncwarp();

            // per-thread base within the K-slice
            const unsigned* Hb = (const unsigned*)(Hf + wid * 128 + ac);

            // software-pipelined: load kt+1 while mma kt
            unsigned a_cur[4][4], a_nxt[4][4];
            #pragma unroll
            for (int mt = 0; mt < 4; ++mt) {
                const unsigned* p = Hb + (size_t)(mt * 16 + ar) * (H_SZ / 2);
                a_cur[mt][0] = __ldcg(p);
                a_cur[mt][1] = __ldcg(p + ROWSTEP8);       // row + 8
                a_cur[mt][2] = __ldcg(p + 4);              // col + 8
                a_cur[mt][3] = __ldcg(p + ROWSTEP8 + 4);   // row+8, col+8
            }
            #pragma unroll
            for (int kt = 0; kt < 8; ++kt) {
                if (kt < 7) {
                    #pragma unroll
                    for (int mt = 0; mt < 4; ++mt) {
                        const unsigned* p = Hb + (kt + 1) * 8
                                          + (size_t)(mt * 16 + ar) * (H_SZ / 2);
                        a_nxt[mt][0] = __ldcg(p);
                        a_nxt[mt][1] = __ldcg(p + ROWSTEP8);
                        a_nxt[mt][2] = __ldcg(p + 4);
                        a_nxt[mt][3] = __ldcg(p + ROWSTEP8 + 4);
                    }
                }
                #pragma unroll
                for (int mt = 0; mt < 4; ++mt)
                    #pragma unroll
                    for (int nt = 0; nt < 4; ++nt)
                        mma16816h(acc[mt][nt], a_cur[mt],
                                  bf[kt][nt * 2], bf[kt][nt * 2 + 1]);
                #pragma unroll
                for (int mt = 0; mt < 4; ++mt)
                    #pragma unroll
                    for (int q = 0; q < 4; ++q) a_cur[mt][q] = a_nxt[mt][q];
            }

            // store this warp's partial [64][34] (float2)
            #pragma unroll
            for (int mt = 0; mt < 4; ++mt) {
                int r0 = mt * 16 + (lane >> 2);
                #pragma unroll
                for (int nt = 0; nt < 4; ++nt) {
                    int col = nt * 8 + (lane & 3) * 2;
                    *(float2*)&Pw[r0 * 34 + col] =
                        make_float2(acc[mt][nt][0], acc[mt][nt][1]);
                    *(float2*)&Pw[(r0 + 8) * 34 + col] =
                        make_float2(acc[mt][nt][2], acc[mt][nt][3]);
                }
            }
        }

        __syncthreads();   // partials visible

        // ---- reduce 8 partials (float2) + gate math (all 256 threads) ----
        float gi0 = xv0.x, gi1 = xv0.y, gf0 = xv1.x, gf1 = xv1.y;
        float go0 = xv2.x, go1 = xv2.y, gc0 = xv3.x, gc1 = xv3.y;
        if (t > 0) {
            #pragma unroll
            for (int w = 0; w < 8; ++w) {
                const float* pr = P + w * 2176 + b2 * 34;
                float2 a0 = *(const float2*)&pr[hq];
                float2 a1 = *(const float2*)&pr[8 + hq];
                float2 a2 = *(const float2*)&pr[16 + hq];
                float2 a3 = *(const float2*)&pr[24 + hq];
                gi0 += a0.x; gi1 += a0.y;
                gf0 += a1.x; gf1 += a1.y;
                go0 += a2.x; go1 += a2.y;
                gc0 += a3.x; gc1 += a3.y;
            }
        }

        float Iv = __fdividef(1.f, 1.f + __expf(-gi0));
        float Fv = __fdividef(1.f, 1.f + __expf(-gf0));
        float Ov = __fdividef(1.f, 1.f + __expf(-go0));
        float Ct = 1.f - __fdividef(2.f, __expf(2.f * gc0) + 1.f);
        c0 = Fv * c0 + Iv * Ct;
        float Hn0 = Ov * (1.f - __fdividef(2.f, __expf(2.f * c0) + 1.f));

        Iv = __fdividef(1.f, 1.f + __expf(-gi1));
        Fv = __fdividef(1.f, 1.f + __expf(-gf1));
        Ov = __fdividef(1.f, 1.f + __expf(-go1));
        Ct = 1.f - __fdividef(2.f, __expf(2.f * gc1) + 1.f);
        c1 = Fv * c1 + Iv * Ct;
        float Hn1 = Ov * (1.f - __fdividef(2.f, __expf(2.f * c1) + 1.f));

        // publish fp16 H (plain stores; release below covers them)
        {
            const int wb = t & 1;
            __half h0h = __float2half_rn(Hn0);
            __half h1h = __float2half_rn(Hn1);
            unsigned hp = (unsigned)*(unsigned short*)&h0h
                        | ((unsigned)*(unsigned short*)&h1h << 16);
            *(unsigned*)&g_Hf[wb][hidx] = hp;
        }
        __syncthreads();       // all H stores happen-before tid0's release
        if (tid == 0) flag_release_add(&g_ready[blockIdx.x]);

        // fp32 outputs after the flag (off the recurrence critical path)
        *(float2*)&out[(size_t)t * BH + hidx] = make_float2(Hn0, Hn1);
        if (t == T_STEPS - 1) {
            size_t base = (size_t)T_STEPS * BH;
            if ((size_t)out_size >= base + (size_t)BH)
                *(float2*)&out[base + hidx] = make_float2(Hn0, Hn1);
            if ((size_t)out_size >= base + 2 * (size_t)BH)
                *(float2*)&out[base + BH + hidx] = make_float2(c0, c1);
        }
    }
}

// ====================================================================
// launch
// ====================================================================
extern "C" void kernel_launch(void* const* d_in, const int* in_sizes, int n_in,
                              void* d_out, int out_size) {
    const float* X   = (const float*)d_in[0];
    const float* Wxi = (const float*)d_in[1];
    const float* Whi = (const float*)d_in[2];
    const float* bi  = (const float*)d_in[3];
    const float* Wxf = (const float*)d_in[4];
    const float* Whf = (const float*)d_in[5];
    const float* bf  = (const float*)d_in[6];
    const float* Wxo = (const float*)d_in[7];
    const float* Who = (const float*)d_in[8];
    const float* bo  = (const float*)d_in[9];
    const float* Wxc = (const float*)d_in[10];
    const float* Whc = (const float*)d_in[11];
    const float* bc  = (const float*)d_in[12];
    float* out = (float*)d_out;

    // Phase 0: convert X / Wx to fp16, build bias concat
    int cblocks = (int)((NX4 + NW4) / 256);
    conv_prep<<<cblocks, 256>>>(X, Wxi, Wxf, Wxo, Wxc, bi, bf, bo, bc);

    // Phase 1: Xg = X @ Wxcat + b, single-pass fp16 (2 CTAs/SM)
    cudaFuncSetAttribute(xg_mma, cudaFuncAttributeMaxDynamicSharedMemorySize,
                         XG_SMEM);
    xg_mma<<<dim3(32, 256), 256, XG_SMEM>>>();

    // Phase 2: persistent recurrence, direct-LDG A operand
    cudaFuncSetAttribute(lstm_rec, cudaFuncAttributeMaxDynamicSharedMemorySize,
                         RT9);
    lstm_rec<<<NCTA, 256, RT9>>>(Whi, Whf, Who, Whc, out, out_size);
}

// round 17
// speedup vs baseline: 1.3550x; 1.3550x over previous
#include <cuda_runtime.h>
#include <cuda_bf16.h>
#include <cuda_fp16.h>
#include <cstdint>
#include <math.h>

// ---------------- problem constants ----------------
#define T_STEPS 512
#define B_SZ    64
#define D_SZ    512
#define H_SZ    1024
#define G4      4096          // 4*H
#define BH      (B_SZ*H_SZ)   // 65536
#define NCTA    128

// ---------------- global scratch / sync state ----------------
__device__ float g_xg[(size_t)T_STEPS * B_SZ * G4];   // 512 MB, Xg = X@Wx + b
__device__ __half g_Hf[2][BH];                        // H fp16, ping-pong
__device__ __half g_Xf[(size_t)T_STEPS * B_SZ * D_SZ];   // X fp16
__device__ __half g_Wxf[(size_t)D_SZ * G4];           // Wx concat fp16
__device__ float g_bcat[G4];                          // bias concat
__device__ int      g_ready[NCTA];                    // per-CTA step counter
__device__ unsigned g_arrive = 0;
__device__ unsigned g_gen    = 0;

// ---------------- helpers ----------------
__device__ __forceinline__ uint32_t smem_u32(const void* p) {
    uint32_t a;
    asm("{ .reg .u64 t; cvta.to.shared.u64 t, %1; cvt.u32.u64 %0, t; }" : "=r"(a) : "l"(p));
    return a;
}
__device__ __forceinline__ void ldsm_x4(uint32_t* r, uint32_t addr) {
    asm volatile("ldmatrix.sync.aligned.m8n8.x4.shared.b16 {%0,%1,%2,%3}, [%4];"
                 : "=r"(r[0]), "=r"(r[1]), "=r"(r[2]), "=r"(r[3]) : "r"(addr));
}
__device__ __forceinline__ void ldsm_x4t(uint32_t* r, uint32_t addr) {
    asm volatile("ldmatrix.sync.aligned.m8n8.x4.trans.shared.b16 {%0,%1,%2,%3}, [%4];"
                 : "=r"(r[0]), "=r"(r[1]), "=r"(r[2]), "=r"(r[3]) : "r"(addr));
}
// fp16 mma
__device__ __forceinline__ void mma16816h(float* c, const uint32_t* a, uint32_t b0, uint32_t b1) {
    asm volatile(
        "mma.sync.aligned.m16n8k16.row.col.f32.f16.f16.f32 "
        "{%0,%1,%2,%3}, {%4,%5,%6,%7}, {%8,%9}, {%0,%1,%2,%3};"
        : "+f"(c[0]), "+f"(c[1]), "+f"(c[2]), "+f"(c[3])
        : "r"(a[0]), "r"(a[1]), "r"(a[2]), "r"(a[3]), "r"(b0), "r"(b1));
}
__device__ __forceinline__ void cp16(uint32_t saddr, const void* g) {
    asm volatile("cp.async.cg.shared.global [%0], [%1], 16;" :: "r"(saddr), "l"(g));
}
#define CP_COMMIT() asm volatile("cp.async.commit_group;" ::: "memory")
#define CP_WAIT(N)  asm volatile("cp.async.wait_group %0;" :: "n"(N) : "memory")

__device__ __forceinline__ void bar_named(int id, int cnt) {
    asm volatile("bar.sync %0, %1;" :: "r"(id), "r"(cnt) : "memory");
}
__device__ __forceinline__ int flag_acq(const int* addr) {
    int v;
    asm volatile("ld.acquire.gpu.s32 %0, [%1];" : "=r"(v) : "l"(addr) : "memory");
    return v;
}
__device__ __forceinline__ void wait_ready_hot(int idx, int target) {
    const int* a = g_ready + idx;
    int spins = 0;
    while (flag_acq(a) < target) {
        if (++spins > 64) __nanosleep(32);
    }
}
// release-increment of this CTA's flag (pairs with consumers' ld.acquire)
__device__ __forceinline__ void flag_release_add(int* addr) {
    asm volatile("red.release.gpu.global.add.s32 [%0], 1;" :: "l"(addr) : "memory");
}

// self-resetting generation barrier (replay-safe)
__device__ __forceinline__ void init_barrier() {
    __syncthreads();
    if (threadIdx.x == 0) {
        __threadfence();
        unsigned gen;
        asm volatile("ld.acquire.gpu.u32 %0, [%1];" : "=r"(gen) : "l"(&g_gen) : "memory");
        unsigned old = atomicAdd(&g_arrive, 1u);
        if (old == NCTA - 1) {
            atomicExch(&g_arrive, 0u);
            __threadfence();
            atomicAdd(&g_gen, 1u);
        } else {
            unsigned cur;
            do {
                __nanosleep(64);
                asm volatile("ld.acquire.gpu.u32 %0, [%1];" : "=r"(cur) : "l"(&g_gen) : "memory");
            } while (cur == gen);
        }
        __threadfence();
    }
    __syncthreads();
}

// ====================================================================
// Kernel 0: convert X and Wx (concat) to fp16; build bias concat.
// (unchanged from passing R13)
// ====================================================================
#define NX4 ((size_t)T_STEPS * B_SZ * D_SZ / 4)      // 4,194,304
#define NW4 ((size_t)D_SZ * G4 / 4)                  // 524,288

__global__ void __launch_bounds__(256) conv_prep(
    const float* __restrict__ X,
    const float* __restrict__ Wx0, const float* __restrict__ Wx1,
    const float* __restrict__ Wx2, const float* __restrict__ Wx3,
    const float* __restrict__ b0p, const float* __restrict__ b1p,
    const float* __restrict__ b2p, const float* __restrict__ b3p)
{
    size_t i = (size_t)blockIdx.x * 256 + threadIdx.x;
    if (i < NX4) {
        float4 v = ((const float4*)X)[i];
        __half h0 = __float2half_rn(v.x), h1 = __float2half_rn(v.y);
        __half h2 = __float2half_rn(v.z), h3 = __float2half_rn(v.w);
        unsigned a = (unsigned)*(unsigned short*)&h0 | ((unsigned)*(unsigned short*)&h1 << 16);
        unsigned b = (unsigned)*(unsigned short*)&h2 | ((unsigned)*(unsigned short*)&h3 << 16);
        *(uint2*)&g_Xf[i * 4] = make_uint2(a, b);
    } else if (i < NX4 + NW4) {
        size_t d = i - NX4;
        int k  = (int)(d >> 10);
        int c4 = (int)(d & 1023);
        int col  = c4 * 4;
        int gate = col >> 10;
        int n    = col & 1023;
        const float* W = (gate == 0) ? Wx0 : (gate == 1) ? Wx1 : (gate == 2) ? Wx2 : Wx3;
        float4 v = *(const float4*)&W[(size_t)k * 1024 + n];
        __half h0 = __float2half_rn(v.x), h1 = __float2half_rn(v.y);
        __half h2 = __float2half_rn(v.z), h3 = __float2half_rn(v.w);
        unsigned a = (unsigned)*(unsigned short*)&h0 | ((unsigned)*(unsigned short*)&h1 << 16);
        unsigned b = (unsigned)*(unsigned short*)&h2 | ((unsigned)*(unsigned short*)&h3 << 16);
        *(uint2*)&g_Wxf[d * 4] = make_uint2(a, b);
    }
    if (i < G4 / 4) {
        int col = (int)i * 4;
        int gate = col >> 10, n = col & 1023;
        const float* bg = (gate == 0) ? b0p : (gate == 1) ? b1p : (gate == 2) ? b2p : b3p;
        ((float4*)g_bcat)[i] = *(const float4*)&bg[n];
    }
}

// ====================================================================
// Kernel 1: Xg = X @ Wxcat + bcat, single-pass fp16 mma.sync.
// (unchanged from passing R13)
// ====================================================================
#define XA(buf) ((buf)*18432)                      // [128][72] fp16
#define XB(buf) (36864 + (buf)*17408)              // [64][136] fp16
#define XG_SMEM 71680

__global__ void __launch_bounds__(256, 2) xg_mma()
{
    extern __shared__ char smc[];
    const uint32_t smem_base = smem_u32(smc);
    const int tid  = threadIdx.x;
    const int wid  = tid >> 5;
    const int lane = tid & 31;
    const int m0   = blockIdx.y * 128;
    const int nb   = blockIdx.x * 128;
    const int mw   = (wid & 3) * 32;
    const int nw   = (wid >> 2) * 64;

    const int arow = ((lane >> 3) & 1) * 8 + (lane & 7);
    const int acol = (lane >> 4) * 8;
    const int brow = ((lane >> 3) & 1) * 8 + (lane & 7);
    const int bcol = (lane >> 4) * 8;

    float acc[2][8][4];
    #pragma unroll
    for (int m = 0; m < 2; ++m)
        #pragma unroll
        for (int n = 0; n < 8; ++n)
            #pragma unroll
            for (int q = 0; q < 4; ++q) acc[m][n][q] = 0.f;

    auto issue_chunk = [&](int s, int buf) {
        #pragma unroll
        for (int i = 0; i < 4; ++i) {
            int idx = tid + i * 256;
            int row = idx >> 3, c8 = (idx & 7) * 8;
            uint32_t sa = smem_base + XA(buf) + (uint32_t)(row * 72 + c8) * 2u;
            cp16(sa, g_Xf + (size_t)(m0 + row) * D_SZ + s * 64 + c8);
        }
        #pragma unroll
        for (int i = 0; i < 4; ++i) {
            int idx = tid + i * 256;
            int r = idx >> 4, c8 = (idx & 15) * 8;
            uint32_t sb = smem_base + XB(buf) + (uint32_t)(r * 136 + c8) * 2u;
            cp16(sb, g_Wxf + (size_t)(s * 64 + r) * G4 + nb + c8);
        }
        CP_COMMIT();
    };

    issue_chunk(0, 0);
    #pragma unroll 1
    for (int s = 0; s < 8; ++s) {
        if (s < 7) { issue_chunk(s + 1, (s + 1) & 1); CP_WAIT(1); }
        else       { CP_WAIT(0); }
        __syncthreads();

        const int buf = s & 1;
        const uint32_t Ah = smem_base + XA(buf);
        const uint32_t Bh = smem_base + XB(buf);
        #pragma unroll
        for (int kt = 0; kt < 4; ++kt) {
            uint32_t ah[2][4];
            #pragma unroll
            for (int m = 0; m < 2; ++m)
                ldsm_x4(ah[m], Ah + (uint32_t)((mw + m * 16 + arow) * 72 + kt * 16 + acol) * 2u);
            uint32_t bh[4][4];
            #pragma unroll
            for (int np = 0; np < 4; ++np)
                ldsm_x4t(bh[np], Bh + (uint32_t)((kt * 16 + brow) * 136 + nw + np * 16 + bcol) * 2u);
            #pragma unroll
            for (int m = 0; m < 2; ++m)
                #pragma unroll
                for (int np = 0; np < 4; ++np) {
                    mma16816h(acc[m][2*np],   ah[m], bh[np][0], bh[np][1]);
                    mma16816h(acc[m][2*np+1], ah[m], bh[np][2], bh[np][3]);
                }
        }
        __syncthreads();
    }

    const int r0    = m0 + mw + (lane >> 2);
    const int cbase = nb + nw + (lane & 3) * 2;
    #pragma unroll
    for (int m = 0; m < 2; ++m) {
        #pragma unroll
        for (int nt = 0; nt < 8; ++nt) {
            int col = cbase + nt * 8;
            float b0 = g_bcat[col], b1 = g_bcat[col + 1];
            int rr = r0 + m * 16;
            float* p0 = g_xg + (size_t)rr * G4 + col;
            float* p1 = g_xg + (size_t)(rr + 8) * G4 + col;
            *(float2*)p0 = make_float2(acc[m][nt][0] + b0, acc[m][nt][1] + b1);
            *(float2*)p1 = make_float2(acc[m][nt][2] + b0, acc[m][nt][3] + b1);
        }
    }
}

// ====================================================================
// Kernel 2: persistent recurrence v10 = R13's v7 structure (best: 4307us)
// + sync-path fixes: (a) no per-thread threadfence -> syncthreads +
// tid0 red.release.gpu; (b) hot-spin flag waits; (c) partials stride 34
// with float2 stores/loads.
// 512 threads / 16 warps; pair (2j,2j+1) shares K-slice j (K=128) and a
// 3-deep shared A-ring; warps split N 16/16; B register-resident.
// ====================================================================

#define RRING 15360                   // per-pair ring: 3 bufs x 5120B
#define RG10  122880                  // partials: 8 x 64 x 34 f32 = 69632
#define RT10  192512                  // total dynamic smem

__global__ void __launch_bounds__(512, 1) lstm_rec(
    const float* __restrict__ Wh0, const float* __restrict__ Wh1,
    const float* __restrict__ Wh2, const float* __restrict__ Wh3,
    float* __restrict__ out, int out_size)
{
    extern __shared__ char smc[];
    const uint32_t smem_base = smem_u32(smc);
    const int tid  = threadIdx.x;
    const int wid  = tid >> 5;
    const int lane = tid & 31;
    const int h0   = blockIdx.x * 8;

    if (tid == 0) g_ready[blockIdx.x] = 0;

    // ---- stage W slice fp16 (stride 40 halves, temp at offset 0) ----
    {
        __half* w = (__half*)smc;
        for (int i = tid; i < 32 * 1024; i += 512) {
            int k = i >> 5, n = i & 31;
            int gate = n >> 3;
            const float* W = (gate == 0) ? Wh0 : (gate == 1) ? Wh1
                             : (gate == 2) ? Wh2 : Wh3;
            w[k * 40 + n] = __float2half_rn(W[(size_t)k * H_SZ + h0 + (n & 7)]);
        }
    }
    __syncthreads();

    // ---- extract register-resident B fragments (once) ----
    const int j     = wid >> 1;        // K-slice 0..7
    const int nhalf = wid & 1;         // N half: cols nhalf*16..+16
    const int brow  = ((lane >> 3) & 1) * 8 + (lane & 7);
    const int bcol0 = (lane >> 4) * 8;
    uint32_t bf[8][4];                 // [k-tile][reg]: 16 cols
    #pragma unroll
    for (int kt = 0; kt < 8; ++kt) {
        uint32_t off = (uint32_t)((j * 128 + kt * 16 + brow) * 40
                                  + nhalf * 16 + bcol0) * 2u;
        ldsm_x4t(bf[kt], smem_base + off);
    }
    init_barrier();   // flags reset visible; W area now reusable as rings

    // ---- ring / ldsm geometry ----
    const uint32_t ring = smem_base + (uint32_t)j * RRING;   // shared by pair
    const int arow  = ((lane >> 3) & 1) * 8 + (lane & 7);
    const uint32_t a_lane = (uint32_t)(arow * 80 + ((lane >> 4) << 4));
    const int barid = 1 + j;
    // epilogue mapping (tid < 256 only)
    const int b2 = tid >> 2;
    const int hq = (tid & 3) * 2;
    const size_t hidx = (size_t)b2 * H_SZ + h0 + hq;

    float* P  = (float*)(smc + RG10);
    float* Pw = P + j * 2176;          // pair's partial [64][34]
    const int colbase = nhalf * 16;

    float c0 = 0.f, c1 = 0.f;

    for (int t = 0; t < T_STEPS; ++t) {
        float acc[4][2][4];
        #pragma unroll
        for (int m = 0; m < 4; ++m)
            #pragma unroll
            for (int n = 0; n < 2; ++n)
                #pragma unroll
                for (int q = 0; q < 4; ++q) acc[m][n][q] = 0.f;

        // ---- Xg prefetch into registers (epilogue threads only) ----
        float2 xv0, xv1, xv2, xv3;
        if (tid < 256) {
            const float* xb = g_xg + ((size_t)t * B_SZ + b2) * G4 + h0 + hq;
            xv0 = __ldcg((const float2*)xb);
            xv1 = __ldcg((const float2*)(xb + 1024));
            xv2 = __ldcg((const float2*)(xb + 2048));
            xv3 = __ldcg((const float2*)(xb + 3072));
        }

        if (t > 0) {
            const __half* Hf = g_Hf[(t - 1) & 1];

            // stage half the rows of chunk sc into ring buf sc%3
            auto stage = [&](int sc) {
                if (lane < 4) wait_ready_hot(j * 16 + sc * 4 + lane, t);
                __syncwarp();
                const uint32_t dst = ring + (uint32_t)(sc % 3) * 5120u;
                const int k0 = j * 128 + sc * 32;
                #pragma unroll
                for (int q = 0; q < 4; ++q) {
                    int idx = q * 32 + lane;                 // 0..127
                    int row = nhalf * 32 + (idx >> 2);
                    int c4  = idx & 3;
                    cp16(dst + (uint32_t)(row * 80 + c4 * 16),
                         Hf + (size_t)row * H_SZ + k0 + c4 * 8);
                }
                CP_COMMIT();
            };

            stage(0); stage(1);

            #pragma unroll
            for (int sc = 0; sc < 4; ++sc) {
                if (sc < 3) CP_WAIT(1); else CP_WAIT(0);
                bar_named(barid, 64);      // partner's half staged + visible
                const uint32_t base = ring + (uint32_t)(sc % 3) * 5120u;
                #pragma unroll
                for (int ktl = 0; ktl < 2; ++ktl) {
                    const int kt = sc * 2 + ktl;
                    #pragma unroll
                    for (int mt = 0; mt < 4; ++mt) {
                        uint32_t av[4];
                        ldsm_x4(av, base + (uint32_t)(mt * 1280)
                                     + (uint32_t)(ktl * 32) + a_lane);
                        #pragma unroll
                        for (int nt = 0; nt < 2; ++nt)
                            mma16816h(acc[mt][nt], av, bf[kt][nt*2], bf[kt][nt*2+1]);
                    }
                }
                if (sc < 2) stage(sc + 2);
            }

            // store this warp's partial columns (stride 34, float2)
            #pragma unroll
            for (int mt = 0; mt < 4; ++mt) {
                int r0 = mt * 16 + (lane >> 2);
                #pragma unroll
                for (int nt = 0; nt < 2; ++nt) {
                    int col = colbase + nt * 8 + (lane & 3) * 2;
                    *(float2*)&Pw[r0 * 34 + col] =
                        make_float2(acc[mt][nt][0], acc[mt][nt][1]);
                    *(float2*)&Pw[(r0 + 8) * 34 + col] =
                        make_float2(acc[mt][nt][2], acc[mt][nt][3]);
                }
            }
        }

        __syncthreads();   // partials visible

        float Hn0 = 0.f, Hn1 = 0.f;
        if (tid < 256) {
            // ---- reduce 8 partials (float2) + gate math ----
            float gi0 = xv0.x, gi1 = xv0.y, gf0 = xv1.x, gf1 = xv1.y;
            float go0 = xv2.x, go1 = xv2.y, gc0 = xv3.x, gc1 = xv3.y;
            if (t > 0) {
                #pragma unroll
                for (int w = 0; w < 8; ++w) {
                    const float* pr = P + w * 2176 + b2 * 34;
                    float2 a0 = *(const float2*)&pr[hq];
                    float2 a1 = *(const float2*)&pr[8 + hq];
                    float2 a2 = *(const float2*)&pr[16 + hq];
                    float2 a3 = *(const float2*)&pr[24 + hq];
                    gi0 += a0.x; gi1 += a0.y;
                    gf0 += a1.x; gf1 += a1.y;
                    go0 += a2.x; go1 += a2.y;
                    gc0 += a3.x; gc1 += a3.y;
                }
            }

            float Iv = __fdividef(1.f, 1.f + __expf(-gi0));
            float Fv = __fdividef(1.f, 1.f + __expf(-gf0));
            float Ov = __fdividef(1.f, 1.f + __expf(-go0));
            float Ct = 1.f - __fdividef(2.f, __expf(2.f * gc0) + 1.f);
            c0 = Fv * c0 + Iv * Ct;
            Hn0 = Ov * (1.f - __fdividef(2.f, __expf(2.f * c0) + 1.f));

            Iv = __fdividef(1.f, 1.f + __expf(-gi1));
            Fv = __fdividef(1.f, 1.f + __expf(-gf1));
            Ov = __fdividef(1.f, 1.f + __expf(-go1));
            Ct = 1.f - __fdividef(2.f, __expf(2.f * gc1) + 1.f);
            c1 = Fv * c1 + Iv * Ct;
            Hn1 = Ov * (1.f - __fdividef(2.f, __expf(2.f * c1) + 1.f));

            // publish fp16 H (plain stores; release below covers them)
            const int wb = t & 1;
            __half h0h = __float2half_rn(Hn0);
            __half h1h = __float2half_rn(Hn1);
            unsigned hp = (unsigned)*(unsigned short*)&h0h
                        | ((unsigned)*(unsigned short*)&h1h << 16);
            *(unsigned*)&g_Hf[wb][hidx] = hp;
        }
        __syncthreads();       // all H stores happen-before tid0's release
        if (tid == 0) flag_release_add(&g_ready[blockIdx.x]);

        // fp32 outputs after the flag (off the recurrence critical path)
        if (tid < 256) {
            *(float2*)&out[(size_t)t * BH + hidx] = make_float2(Hn0, Hn1);
            if (t == T_STEPS - 1) {
                size_t base = (size_t)T_STEPS * BH;
                if ((size_t)out_size >= base + (size_t)BH)
                    *(float2*)&out[base + hidx] = make_float2(Hn0, Hn1);
                if ((size_t)out_size >= base + 2 * (size_t)BH)
                    *(float2*)&out[base + BH + hidx] = make_float2(c0, c1);
            }
        }
    }
}

// ====================================================================
// launch
// ====================================================================
extern "C" void kernel_launch(void* const* d_in, const int* in_sizes, int n_in,
                              void* d_out, int out_size) {
    const float* X   = (const float*)d_in[0];
    const float* Wxi = (const float*)d_in[1];
    const float* Whi = (const float*)d_in[2];
    const float* bi  = (const float*)d_in[3];
    const float* Wxf = (const float*)d_in[4];
    const float* Whf = (const float*)d_in[5];
    const float* bf  = (const float*)d_in[6];
    const float* Wxo = (const float*)d_in[7];
    const float* Who = (const float*)d_in[8];
    const float* bo  = (const float*)d_in[9];
    const float* Wxc = (const float*)d_in[10];
    const float* Whc = (const float*)d_in[11];
    const float* bc  = (const float*)d_in[12];
    float* out = (float*)d_out;

    // Phase 0: convert X / Wx to fp16, build bias concat
    int cblocks = (int)((NX4 + NW4) / 256);
    conv_prep<<<cblocks, 256>>>(X, Wxi, Wxf, Wxo, Wxc, bi, bf, bo, bc);

    // Phase 1: Xg = X @ Wxcat + b, single-pass fp16 (2 CTAs/SM)
    cudaFuncSetAttribute(xg_mma, cudaFuncAttributeMaxDynamicSharedMemorySize,
                         XG_SMEM);
    xg_mma<<<dim3(32, 256), 256, XG_SMEM>>>();

    // Phase 2: persistent recurrence, v7 structure + fast sync path
    cudaFuncSetAttribute(lstm_rec, cudaFuncAttributeMaxDynamicSharedMemorySize,
                         RT10);
    lstm_rec<<<NCTA, 512, RT10>>>(Whi, Whf, Who, Whc, out, out_size);
}